// round 14
// baseline (speedup 1.0000x reference)
#include <cuda_runtime.h>
#include <cuda_pipeline.h>
#include <math.h>

#define LAMBDA 1.5f
#define B_SZ 32
#define N_SZ 2048
#define HID 256
#define THREADS 128
#define WARPS_PER_BLOCK 4   // one output row per warp, 4 rows per block

// ---------------------------------------------------------------------------
// R12 warp structure (best: 150.3us, DRAM 90.1%) with HALF-SIZE blocks:
// 128 threads / 4 warps / 4 rows, 16384 blocks, 12 blocks/SM. Per-block
// wall time halves (~16us -> ~8us) so the final partial wave wastes ~6us
// instead of ~12us. Same cp.async x-staging + depth-2 cross-barrier Y
// prefetch; identical inner loop.
// ---------------------------------------------------------------------------
__global__ __launch_bounds__(THREADS, 12) void fused_kernel(
    const float* __restrict__ Yr, const float* __restrict__ Yi,
    const float* __restrict__ xr, const float* __restrict__ xi,
    const float* __restrict__ xpr, const float* __restrict__ xpi,
    const float* __restrict__ d3w, const float* __restrict__ d3b,
    const float* __restrict__ w1, const float* __restrict__ b1,
    const float* __restrict__ w2, const float* __restrict__ b2,
    float* __restrict__ out) {

    __shared__ float sxr[N_SZ];
    __shared__ float sxi[N_SZ];
    __shared__ float sw1[HID];
    __shared__ float sb1[HID];
    __shared__ float sw2[HID];

    const int tid = threadIdx.x;
    const int b = blockIdx.y;
    const int wid = tid >> 5;
    const int lid = tid & 31;
    const int n = blockIdx.x * WARPS_PER_BLOCK + wid;

    const size_t row_base = (((size_t)b * N_SZ) + n) * N_SZ;
    const float4* yr4 = (const float4*)(Yr + row_base);
    const float4* yi4 = (const float4*)(Yi + row_base);

    // ---- PREFETCH depth 2: first two k-iterations' Y loads ----
    const float4 a_p0 = yr4[lid];
    const float4 c_p0 = yi4[lid];
    const float4 a_p1 = yr4[lid + 32];
    const float4 c_p1 = yi4[lid + 32];

    // Hoist scalar epilogue params (overlap staging too)
    const float dw  = d3w[0];
    const float db  = d3b[0];
    const float b2v = b2[0];
    const size_t idx = (size_t)b * N_SZ + n;
    const float xpr_v = xpr[idx];
    const float xpi_v = xpi[idx];

    // ---- Stage x + MLP weights into shared via cp.async (no reg traffic) --
    {
        const float4* xr4 = (const float4*)(xr + (size_t)b * N_SZ);
        const float4* xi4 = (const float4*)(xi + (size_t)b * N_SZ);
        #pragma unroll
        for (int k = tid; k < N_SZ / 4; k += THREADS) {
            __pipeline_memcpy_async(&((float4*)sxr)[k], &xr4[k], 16);
            __pipeline_memcpy_async(&((float4*)sxi)[k], &xi4[k], 16);
        }
        #pragma unroll
        for (int j = tid; j < HID; j += THREADS) {
            __pipeline_memcpy_async(&sw1[j], &w1[j], 4);
            __pipeline_memcpy_async(&sb1[j], &b1[j], 4);
            __pipeline_memcpy_async(&sw2[j], &w2[j], 4);
        }
        __pipeline_commit();
        __pipeline_wait_prior(0);
    }
    __syncthreads();

    const float4* sxr4 = (const float4*)sxr;
    const float4* sxi4 = (const float4*)sxi;

    float rr = 0.f, ii = 0.f, ri = 0.f, ir = 0.f, ss = 0.f;

    // ---- Consume the two prefetched iterations ----
    {
        float4 u = sxr4[lid];
        float4 v = sxi4[lid];
        rr = fmaf(a_p0.x, u.x, rr); rr = fmaf(a_p0.y, u.y, rr);
        rr = fmaf(a_p0.z, u.z, rr); rr = fmaf(a_p0.w, u.w, rr);
        ii = fmaf(c_p0.x, v.x, ii); ii = fmaf(c_p0.y, v.y, ii);
        ii = fmaf(c_p0.z, v.z, ii); ii = fmaf(c_p0.w, v.w, ii);
        ri = fmaf(a_p0.x, v.x, ri); ri = fmaf(a_p0.y, v.y, ri);
        ri = fmaf(a_p0.z, v.z, ri); ri = fmaf(a_p0.w, v.w, ri);
        ir = fmaf(c_p0.x, u.x, ir); ir = fmaf(c_p0.y, u.y, ir);
        ir = fmaf(c_p0.z, u.z, ir); ir = fmaf(c_p0.w, u.w, ir);
        ss = fmaf(u.x, u.x, ss); ss = fmaf(u.y, u.y, ss);
        ss = fmaf(u.z, u.z, ss); ss = fmaf(u.w, u.w, ss);
        ss = fmaf(v.x, v.x, ss); ss = fmaf(v.y, v.y, ss);
        ss = fmaf(v.z, v.z, ss); ss = fmaf(v.w, v.w, ss);
    }
    {
        float4 u = sxr4[lid + 32];
        float4 v = sxi4[lid + 32];
        rr = fmaf(a_p1.x, u.x, rr); rr = fmaf(a_p1.y, u.y, rr);
        rr = fmaf(a_p1.z, u.z, rr); rr = fmaf(a_p1.w, u.w, rr);
        ii = fmaf(c_p1.x, v.x, ii); ii = fmaf(c_p1.y, v.y, ii);
        ii = fmaf(c_p1.z, v.z, ii); ii = fmaf(c_p1.w, v.w, ii);
        ri = fmaf(a_p1.x, v.x, ri); ri = fmaf(a_p1.y, v.y, ri);
        ri = fmaf(a_p1.z, v.z, ri); ri = fmaf(a_p1.w, v.w, ri);
        ir = fmaf(c_p1.x, u.x, ir); ir = fmaf(c_p1.y, u.y, ir);
        ir = fmaf(c_p1.z, u.z, ir); ir = fmaf(c_p1.w, u.w, ir);
        ss = fmaf(u.x, u.x, ss); ss = fmaf(u.y, u.y, ss);
        ss = fmaf(u.z, u.z, ss); ss = fmaf(u.w, u.w, ss);
        ss = fmaf(v.x, v.x, ss); ss = fmaf(v.y, v.y, ss);
        ss = fmaf(v.z, v.z, ss); ss = fmaf(v.w, v.w, ss);
    }

    // ---- Remaining 14 iterations, fully unrolled ----
    #pragma unroll 14
    for (int k = lid + 64; k < N_SZ / 4; k += 32) {
        float4 a = yr4[k];
        float4 c = yi4[k];
        float4 u = sxr4[k];
        float4 v = sxi4[k];
        rr = fmaf(a.x, u.x, rr); rr = fmaf(a.y, u.y, rr);
        rr = fmaf(a.z, u.z, rr); rr = fmaf(a.w, u.w, rr);
        ii = fmaf(c.x, v.x, ii); ii = fmaf(c.y, v.y, ii);
        ii = fmaf(c.z, v.z, ii); ii = fmaf(c.w, v.w, ii);
        ri = fmaf(a.x, v.x, ri); ri = fmaf(a.y, v.y, ri);
        ri = fmaf(a.z, v.z, ri); ri = fmaf(a.w, v.w, ri);
        ir = fmaf(c.x, u.x, ir); ir = fmaf(c.y, u.y, ir);
        ir = fmaf(c.z, u.z, ir); ir = fmaf(c.w, u.w, ir);
        ss = fmaf(u.x, u.x, ss); ss = fmaf(u.y, u.y, ss);
        ss = fmaf(u.z, u.z, ss); ss = fmaf(u.w, u.w, ss);
        ss = fmaf(v.x, v.x, ss); ss = fmaf(v.y, v.y, ss);
        ss = fmaf(v.z, v.z, ss); ss = fmaf(v.w, v.w, ss);
    }

    // butterfly reduce all five accumulators -> every lane has full sums
    #pragma unroll
    for (int off = 16; off > 0; off >>= 1) {
        rr += __shfl_xor_sync(0xFFFFFFFFu, rr, off);
        ii += __shfl_xor_sync(0xFFFFFFFFu, ii, off);
        ri += __shfl_xor_sync(0xFFFFFFFFu, ri, off);
        ir += __shfl_xor_sync(0xFFFFFFFFu, ir, off);
        ss += __shfl_xor_sync(0xFFFFFFFFu, ss, off);
    }

    // ---- Epilogue (per-warp; no cross-warp communication needed) ----
    const float sc = -(LAMBDA * LAMBDA) * (1.0f - ss / (float)N_SZ);

    float x1r = fmaf(LAMBDA * (rr - ii), dw, db);
    float x1i = fmaf(LAMBDA * (ri + ir), dw, db);
    x1r = fmaf(sc, xpr_v, x1r);
    x1i = fmaf(sc, xpi_v, x1i);

    const float xabs = sqrtf(x1r * x1r + x1i * x1i);

    // MLP: 256 hidden units, 8 per lane
    float partial = 0.f;
    #pragma unroll
    for (int j = lid; j < HID; j += 32) {
        float h = fmaxf(fmaf(xabs, sw1[j], sb1[j]), 0.f);
        partial = fmaf(h, sw2[j], partial);
    }
    #pragma unroll
    for (int off = 16; off > 0; off >>= 1)
        partial += __shfl_xor_sync(0xFFFFFFFFu, partial, off);

    if (lid == 0) {
        float g = tanhf(partial + b2v);
        float q = g / fmaxf(xabs, 1e-12f);
        out[idx] = x1r * q;                          // real part
        out[(size_t)B_SZ * N_SZ + idx] = x1i * q;    // imag part
    }
}

extern "C" void kernel_launch(void* const* d_in, const int* in_sizes, int n_in,
                              void* d_out, int out_size) {
    const float* Yr  = (const float*)d_in[0];
    const float* Yi  = (const float*)d_in[1];
    const float* xr  = (const float*)d_in[2];
    const float* xi  = (const float*)d_in[3];
    const float* xpr = (const float*)d_in[4];
    const float* xpi = (const float*)d_in[5];
    const float* d3w = (const float*)d_in[6];
    const float* d3b = (const float*)d_in[7];
    const float* w1  = (const float*)d_in[8];
    const float* b1  = (const float*)d_in[9];
    const float* w2  = (const float*)d_in[10];
    const float* b2  = (const float*)d_in[11];
    float* out = (float*)d_out;

    dim3 grid(N_SZ / WARPS_PER_BLOCK, B_SZ);
    fused_kernel<<<grid, THREADS>>>(Yr, Yi, xr, xi, xpr, xpi,
                                    d3w, d3b, w1, b1, w2, b2, out);
}

// round 15
// speedup vs baseline: 1.1703x; 1.1703x over previous
#include <cuda_runtime.h>
#include <cuda_pipeline.h>
#include <math.h>

#define LAMBDA 1.5f
#define B_SZ 32
#define N_SZ 2048
#define HID 256
#define THREADS 256
#define WARPS_PER_BLOCK 8   // one output row per warp

// ---------------------------------------------------------------------------
// R12 (best: 150.3us, DRAM 90.1%) with cross-barrier Y prefetch deepened to
// THREE k-iterations (6x LDG.128 issued before cp.async staging), covering
// ~1800 cycles of DRAM latency during the block prologue. Block shape is
// frozen at the measured optimum: 8192 blocks x 256 thr x 6/SM (R7/R10/R14
// all showed both larger and smaller block shapes lose 15-20%).
// ---------------------------------------------------------------------------
__global__ __launch_bounds__(THREADS, 6) void fused_kernel(
    const float* __restrict__ Yr, const float* __restrict__ Yi,
    const float* __restrict__ xr, const float* __restrict__ xi,
    const float* __restrict__ xpr, const float* __restrict__ xpi,
    const float* __restrict__ d3w, const float* __restrict__ d3b,
    const float* __restrict__ w1, const float* __restrict__ b1,
    const float* __restrict__ w2, const float* __restrict__ b2,
    float* __restrict__ out) {

    __shared__ float sxr[N_SZ];
    __shared__ float sxi[N_SZ];
    __shared__ float sw1[HID];
    __shared__ float sb1[HID];
    __shared__ float sw2[HID];

    const int tid = threadIdx.x;
    const int b = blockIdx.y;
    const int wid = tid >> 5;
    const int lid = tid & 31;
    const int n = blockIdx.x * WARPS_PER_BLOCK + wid;

    const size_t row_base = (((size_t)b * N_SZ) + n) * N_SZ;
    const float4* yr4 = (const float4*)(Yr + row_base);
    const float4* yi4 = (const float4*)(Yi + row_base);

    // ---- PREFETCH depth 3: first three k-iterations' Y loads ----
    const float4 a_p0 = yr4[lid];
    const float4 c_p0 = yi4[lid];
    const float4 a_p1 = yr4[lid + 32];
    const float4 c_p1 = yi4[lid + 32];
    const float4 a_p2 = yr4[lid + 64];
    const float4 c_p2 = yi4[lid + 64];

    // Hoist scalar epilogue params (overlap staging too)
    const float dw  = d3w[0];
    const float db  = d3b[0];
    const float b2v = b2[0];
    const size_t idx = (size_t)b * N_SZ + n;
    const float xpr_v = xpr[idx];
    const float xpi_v = xpi[idx];

    // ---- Stage x + MLP weights into shared via cp.async (no reg traffic) --
    {
        const float4* xr4 = (const float4*)(xr + (size_t)b * N_SZ);
        const float4* xi4 = (const float4*)(xi + (size_t)b * N_SZ);
        #pragma unroll
        for (int k = tid; k < N_SZ / 4; k += THREADS) {
            __pipeline_memcpy_async(&((float4*)sxr)[k], &xr4[k], 16);
            __pipeline_memcpy_async(&((float4*)sxi)[k], &xi4[k], 16);
        }
        if (tid < HID) {
            __pipeline_memcpy_async(&sw1[tid], &w1[tid], 4);
            __pipeline_memcpy_async(&sb1[tid], &b1[tid], 4);
            __pipeline_memcpy_async(&sw2[tid], &w2[tid], 4);
        }
        __pipeline_commit();
        __pipeline_wait_prior(0);
    }
    __syncthreads();

    const float4* sxr4 = (const float4*)sxr;
    const float4* sxi4 = (const float4*)sxi;

    float rr = 0.f, ii = 0.f, ri = 0.f, ir = 0.f, ss = 0.f;

    // ---- Consume the three prefetched iterations ----
    {
        float4 u = sxr4[lid];
        float4 v = sxi4[lid];
        rr = fmaf(a_p0.x, u.x, rr); rr = fmaf(a_p0.y, u.y, rr);
        rr = fmaf(a_p0.z, u.z, rr); rr = fmaf(a_p0.w, u.w, rr);
        ii = fmaf(c_p0.x, v.x, ii); ii = fmaf(c_p0.y, v.y, ii);
        ii = fmaf(c_p0.z, v.z, ii); ii = fmaf(c_p0.w, v.w, ii);
        ri = fmaf(a_p0.x, v.x, ri); ri = fmaf(a_p0.y, v.y, ri);
        ri = fmaf(a_p0.z, v.z, ri); ri = fmaf(a_p0.w, v.w, ri);
        ir = fmaf(c_p0.x, u.x, ir); ir = fmaf(c_p0.y, u.y, ir);
        ir = fmaf(c_p0.z, u.z, ir); ir = fmaf(c_p0.w, u.w, ir);
        ss = fmaf(u.x, u.x, ss); ss = fmaf(u.y, u.y, ss);
        ss = fmaf(u.z, u.z, ss); ss = fmaf(u.w, u.w, ss);
        ss = fmaf(v.x, v.x, ss); ss = fmaf(v.y, v.y, ss);
        ss = fmaf(v.z, v.z, ss); ss = fmaf(v.w, v.w, ss);
    }
    {
        float4 u = sxr4[lid + 32];
        float4 v = sxi4[lid + 32];
        rr = fmaf(a_p1.x, u.x, rr); rr = fmaf(a_p1.y, u.y, rr);
        rr = fmaf(a_p1.z, u.z, rr); rr = fmaf(a_p1.w, u.w, rr);
        ii = fmaf(c_p1.x, v.x, ii); ii = fmaf(c_p1.y, v.y, ii);
        ii = fmaf(c_p1.z, v.z, ii); ii = fmaf(c_p1.w, v.w, ii);
        ri = fmaf(a_p1.x, v.x, ri); ri = fmaf(a_p1.y, v.y, ri);
        ri = fmaf(a_p1.z, v.z, ri); ri = fmaf(a_p1.w, v.w, ri);
        ir = fmaf(c_p1.x, u.x, ir); ir = fmaf(c_p1.y, u.y, ir);
        ir = fmaf(c_p1.z, u.z, ir); ir = fmaf(c_p1.w, u.w, ir);
        ss = fmaf(u.x, u.x, ss); ss = fmaf(u.y, u.y, ss);
        ss = fmaf(u.z, u.z, ss); ss = fmaf(u.w, u.w, ss);
        ss = fmaf(v.x, v.x, ss); ss = fmaf(v.y, v.y, ss);
        ss = fmaf(v.z, v.z, ss); ss = fmaf(v.w, v.w, ss);
    }
    {
        float4 u = sxr4[lid + 64];
        float4 v = sxi4[lid + 64];
        rr = fmaf(a_p2.x, u.x, rr); rr = fmaf(a_p2.y, u.y, rr);
        rr = fmaf(a_p2.z, u.z, rr); rr = fmaf(a_p2.w, u.w, rr);
        ii = fmaf(c_p2.x, v.x, ii); ii = fmaf(c_p2.y, v.y, ii);
        ii = fmaf(c_p2.z, v.z, ii); ii = fmaf(c_p2.w, v.w, ii);
        ri = fmaf(a_p2.x, v.x, ri); ri = fmaf(a_p2.y, v.y, ri);
        ri = fmaf(a_p2.z, v.z, ri); ri = fmaf(a_p2.w, v.w, ri);
        ir = fmaf(c_p2.x, u.x, ir); ir = fmaf(c_p2.y, u.y, ir);
        ir = fmaf(c_p2.z, u.z, ir); ir = fmaf(c_p2.w, u.w, ir);
        ss = fmaf(u.x, u.x, ss); ss = fmaf(u.y, u.y, ss);
        ss = fmaf(u.z, u.z, ss); ss = fmaf(u.w, u.w, ss);
        ss = fmaf(v.x, v.x, ss); ss = fmaf(v.y, v.y, ss);
        ss = fmaf(v.z, v.z, ss); ss = fmaf(v.w, v.w, ss);
    }

    // ---- Remaining 13 iterations, fully unrolled ----
    #pragma unroll 13
    for (int k = lid + 96; k < N_SZ / 4; k += 32) {
        float4 a = yr4[k];
        float4 c = yi4[k];
        float4 u = sxr4[k];
        float4 v = sxi4[k];
        rr = fmaf(a.x, u.x, rr); rr = fmaf(a.y, u.y, rr);
        rr = fmaf(a.z, u.z, rr); rr = fmaf(a.w, u.w, rr);
        ii = fmaf(c.x, v.x, ii); ii = fmaf(c.y, v.y, ii);
        ii = fmaf(c.z, v.z, ii); ii = fmaf(c.w, v.w, ii);
        ri = fmaf(a.x, v.x, ri); ri = fmaf(a.y, v.y, ri);
        ri = fmaf(a.z, v.z, ri); ri = fmaf(a.w, v.w, ri);
        ir = fmaf(c.x, u.x, ir); ir = fmaf(c.y, u.y, ir);
        ir = fmaf(c.z, u.z, ir); ir = fmaf(c.w, u.w, ir);
        ss = fmaf(u.x, u.x, ss); ss = fmaf(u.y, u.y, ss);
        ss = fmaf(u.z, u.z, ss); ss = fmaf(u.w, u.w, ss);
        ss = fmaf(v.x, v.x, ss); ss = fmaf(v.y, v.y, ss);
        ss = fmaf(v.z, v.z, ss); ss = fmaf(v.w, v.w, ss);
    }

    // butterfly reduce all five accumulators -> every lane has full sums
    #pragma unroll
    for (int off = 16; off > 0; off >>= 1) {
        rr += __shfl_xor_sync(0xFFFFFFFFu, rr, off);
        ii += __shfl_xor_sync(0xFFFFFFFFu, ii, off);
        ri += __shfl_xor_sync(0xFFFFFFFFu, ri, off);
        ir += __shfl_xor_sync(0xFFFFFFFFu, ir, off);
        ss += __shfl_xor_sync(0xFFFFFFFFu, ss, off);
    }

    // ---- Epilogue (per-warp; no cross-warp communication needed) ----
    const float sc = -(LAMBDA * LAMBDA) * (1.0f - ss / (float)N_SZ);

    float x1r = fmaf(LAMBDA * (rr - ii), dw, db);
    float x1i = fmaf(LAMBDA * (ri + ir), dw, db);
    x1r = fmaf(sc, xpr_v, x1r);
    x1i = fmaf(sc, xpi_v, x1i);

    const float xabs = sqrtf(x1r * x1r + x1i * x1i);

    // MLP: 256 hidden units, 8 per lane
    float partial = 0.f;
    #pragma unroll
    for (int j = lid; j < HID; j += 32) {
        float h = fmaxf(fmaf(xabs, sw1[j], sb1[j]), 0.f);
        partial = fmaf(h, sw2[j], partial);
    }
    #pragma unroll
    for (int off = 16; off > 0; off >>= 1)
        partial += __shfl_xor_sync(0xFFFFFFFFu, partial, off);

    if (lid == 0) {
        float g = tanhf(partial + b2v);
        float q = g / fmaxf(xabs, 1e-12f);
        out[idx] = x1r * q;                          // real part
        out[(size_t)B_SZ * N_SZ + idx] = x1i * q;    // imag part
    }
}

extern "C" void kernel_launch(void* const* d_in, const int* in_sizes, int n_in,
                              void* d_out, int out_size) {
    const float* Yr  = (const float*)d_in[0];
    const float* Yi  = (const float*)d_in[1];
    const float* xr  = (const float*)d_in[2];
    const float* xi  = (const float*)d_in[3];
    const float* xpr = (const float*)d_in[4];
    const float* xpi = (const float*)d_in[5];
    const float* d3w = (const float*)d_in[6];
    const float* d3b = (const float*)d_in[7];
    const float* w1  = (const float*)d_in[8];
    const float* b1  = (const float*)d_in[9];
    const float* w2  = (const float*)d_in[10];
    const float* b2  = (const float*)d_in[11];
    float* out = (float*)d_out;

    dim3 grid(N_SZ / WARPS_PER_BLOCK, B_SZ);
    fused_kernel<<<grid, THREADS>>>(Yr, Yi, xr, xi, xpr, xpi,
                                    d3w, d3b, w1, b1, w2, b2, out);
}

// round 16
// speedup vs baseline: 1.2025x; 1.0275x over previous
#include <cuda_runtime.h>
#include <cuda_pipeline.h>
#include <math.h>

#define LAMBDA 1.5f
#define B_SZ 32
#define N_SZ 2048
#define HID 256
#define THREADS 256
#define WARPS_PER_BLOCK 8   // one output row per warp

// ---------------------------------------------------------------------------
// FINAL (= R12, measured best: 150.3us, DRAM 90.1%, 7.14 TB/s effective).
// Fully fused complex matvec + per-batch scale + Dense(1) + scale*x_prev +
// 256-wide MLP + tanh + normalize, one kernel, Y streamed exactly once.
// Measured design points (16 rounds):
//  - block shape 8192 x 256thr x 6/SM is a sharp optimum (R7/R10/R14)
//  - plain LDG.128 beats __ldcs (R3/R4); smem-x beats L1-x (R13)
//  - |x|^2 fused into the streaming loop as a 5th accumulator (R6)
//  - full 16-iter unroll maximizes per-warp in-flight loads (R8/R9)
//  - cp.async staging + depth-2 cross-barrier Y prefetch (R11/R12);
//    depth 3 regresses via register pressure (R15)
// ---------------------------------------------------------------------------
__global__ __launch_bounds__(THREADS, 6) void fused_kernel(
    const float* __restrict__ Yr, const float* __restrict__ Yi,
    const float* __restrict__ xr, const float* __restrict__ xi,
    const float* __restrict__ xpr, const float* __restrict__ xpi,
    const float* __restrict__ d3w, const float* __restrict__ d3b,
    const float* __restrict__ w1, const float* __restrict__ b1,
    const float* __restrict__ w2, const float* __restrict__ b2,
    float* __restrict__ out) {

    __shared__ float sxr[N_SZ];
    __shared__ float sxi[N_SZ];
    __shared__ float sw1[HID];
    __shared__ float sb1[HID];
    __shared__ float sw2[HID];

    const int tid = threadIdx.x;
    const int b = blockIdx.y;
    const int wid = tid >> 5;
    const int lid = tid & 31;
    const int n = blockIdx.x * WARPS_PER_BLOCK + wid;

    const size_t row_base = (((size_t)b * N_SZ) + n) * N_SZ;
    const float4* yr4 = (const float4*)(Yr + row_base);
    const float4* yi4 = (const float4*)(Yi + row_base);

    // ---- PREFETCH depth 2: first two k-iterations' Y loads ----
    const float4 a_p0 = yr4[lid];
    const float4 c_p0 = yi4[lid];
    const float4 a_p1 = yr4[lid + 32];
    const float4 c_p1 = yi4[lid + 32];

    // Hoist scalar epilogue params (overlap staging too)
    const float dw  = d3w[0];
    const float db  = d3b[0];
    const float b2v = b2[0];
    const size_t idx = (size_t)b * N_SZ + n;
    const float xpr_v = xpr[idx];
    const float xpi_v = xpi[idx];

    // ---- Stage x + MLP weights into shared via cp.async (no reg traffic) --
    {
        const float4* xr4 = (const float4*)(xr + (size_t)b * N_SZ);
        const float4* xi4 = (const float4*)(xi + (size_t)b * N_SZ);
        #pragma unroll
        for (int k = tid; k < N_SZ / 4; k += THREADS) {
            __pipeline_memcpy_async(&((float4*)sxr)[k], &xr4[k], 16);
            __pipeline_memcpy_async(&((float4*)sxi)[k], &xi4[k], 16);
        }
        if (tid < HID) {
            __pipeline_memcpy_async(&sw1[tid], &w1[tid], 4);
            __pipeline_memcpy_async(&sb1[tid], &b1[tid], 4);
            __pipeline_memcpy_async(&sw2[tid], &w2[tid], 4);
        }
        __pipeline_commit();
        __pipeline_wait_prior(0);
    }
    __syncthreads();

    const float4* sxr4 = (const float4*)sxr;
    const float4* sxi4 = (const float4*)sxi;

    float rr = 0.f, ii = 0.f, ri = 0.f, ir = 0.f, ss = 0.f;

    // ---- Consume the two prefetched iterations ----
    {
        float4 u = sxr4[lid];
        float4 v = sxi4[lid];
        rr = fmaf(a_p0.x, u.x, rr); rr = fmaf(a_p0.y, u.y, rr);
        rr = fmaf(a_p0.z, u.z, rr); rr = fmaf(a_p0.w, u.w, rr);
        ii = fmaf(c_p0.x, v.x, ii); ii = fmaf(c_p0.y, v.y, ii);
        ii = fmaf(c_p0.z, v.z, ii); ii = fmaf(c_p0.w, v.w, ii);
        ri = fmaf(a_p0.x, v.x, ri); ri = fmaf(a_p0.y, v.y, ri);
        ri = fmaf(a_p0.z, v.z, ri); ri = fmaf(a_p0.w, v.w, ri);
        ir = fmaf(c_p0.x, u.x, ir); ir = fmaf(c_p0.y, u.y, ir);
        ir = fmaf(c_p0.z, u.z, ir); ir = fmaf(c_p0.w, u.w, ir);
        ss = fmaf(u.x, u.x, ss); ss = fmaf(u.y, u.y, ss);
        ss = fmaf(u.z, u.z, ss); ss = fmaf(u.w, u.w, ss);
        ss = fmaf(v.x, v.x, ss); ss = fmaf(v.y, v.y, ss);
        ss = fmaf(v.z, v.z, ss); ss = fmaf(v.w, v.w, ss);
    }
    {
        float4 u = sxr4[lid + 32];
        float4 v = sxi4[lid + 32];
        rr = fmaf(a_p1.x, u.x, rr); rr = fmaf(a_p1.y, u.y, rr);
        rr = fmaf(a_p1.z, u.z, rr); rr = fmaf(a_p1.w, u.w, rr);
        ii = fmaf(c_p1.x, v.x, ii); ii = fmaf(c_p1.y, v.y, ii);
        ii = fmaf(c_p1.z, v.z, ii); ii = fmaf(c_p1.w, v.w, ii);
        ri = fmaf(a_p1.x, v.x, ri); ri = fmaf(a_p1.y, v.y, ri);
        ri = fmaf(a_p1.z, v.z, ri); ri = fmaf(a_p1.w, v.w, ri);
        ir = fmaf(c_p1.x, u.x, ir); ir = fmaf(c_p1.y, u.y, ir);
        ir = fmaf(c_p1.z, u.z, ir); ir = fmaf(c_p1.w, u.w, ir);
        ss = fmaf(u.x, u.x, ss); ss = fmaf(u.y, u.y, ss);
        ss = fmaf(u.z, u.z, ss); ss = fmaf(u.w, u.w, ss);
        ss = fmaf(v.x, v.x, ss); ss = fmaf(v.y, v.y, ss);
        ss = fmaf(v.z, v.z, ss); ss = fmaf(v.w, v.w, ss);
    }

    // ---- Remaining 14 iterations, fully unrolled ----
    #pragma unroll 14
    for (int k = lid + 64; k < N_SZ / 4; k += 32) {
        float4 a = yr4[k];
        float4 c = yi4[k];
        float4 u = sxr4[k];
        float4 v = sxi4[k];
        rr = fmaf(a.x, u.x, rr); rr = fmaf(a.y, u.y, rr);
        rr = fmaf(a.z, u.z, rr); rr = fmaf(a.w, u.w, rr);
        ii = fmaf(c.x, v.x, ii); ii = fmaf(c.y, v.y, ii);
        ii = fmaf(c.z, v.z, ii); ii = fmaf(c.w, v.w, ii);
        ri = fmaf(a.x, v.x, ri); ri = fmaf(a.y, v.y, ri);
        ri = fmaf(a.z, v.z, ri); ri = fmaf(a.w, v.w, ri);
        ir = fmaf(c.x, u.x, ir); ir = fmaf(c.y, u.y, ir);
        ir = fmaf(c.z, u.z, ir); ir = fmaf(c.w, u.w, ir);
        ss = fmaf(u.x, u.x, ss); ss = fmaf(u.y, u.y, ss);
        ss = fmaf(u.z, u.z, ss); ss = fmaf(u.w, u.w, ss);
        ss = fmaf(v.x, v.x, ss); ss = fmaf(v.y, v.y, ss);
        ss = fmaf(v.z, v.z, ss); ss = fmaf(v.w, v.w, ss);
    }

    // butterfly reduce all five accumulators -> every lane has full sums
    #pragma unroll
    for (int off = 16; off > 0; off >>= 1) {
        rr += __shfl_xor_sync(0xFFFFFFFFu, rr, off);
        ii += __shfl_xor_sync(0xFFFFFFFFu, ii, off);
        ri += __shfl_xor_sync(0xFFFFFFFFu, ri, off);
        ir += __shfl_xor_sync(0xFFFFFFFFu, ir, off);
        ss += __shfl_xor_sync(0xFFFFFFFFu, ss, off);
    }

    // ---- Epilogue (per-warp; no cross-warp communication needed) ----
    const float sc = -(LAMBDA * LAMBDA) * (1.0f - ss / (float)N_SZ);

    float x1r = fmaf(LAMBDA * (rr - ii), dw, db);
    float x1i = fmaf(LAMBDA * (ri + ir), dw, db);
    x1r = fmaf(sc, xpr_v, x1r);
    x1i = fmaf(sc, xpi_v, x1i);

    const float xabs = sqrtf(x1r * x1r + x1i * x1i);

    // MLP: 256 hidden units, 8 per lane
    float partial = 0.f;
    #pragma unroll
    for (int j = lid; j < HID; j += 32) {
        float h = fmaxf(fmaf(xabs, sw1[j], sb1[j]), 0.f);
        partial = fmaf(h, sw2[j], partial);
    }
    #pragma unroll
    for (int off = 16; off > 0; off >>= 1)
        partial += __shfl_xor_sync(0xFFFFFFFFu, partial, off);

    if (lid == 0) {
        float g = tanhf(partial + b2v);
        float q = g / fmaxf(xabs, 1e-12f);
        out[idx] = x1r * q;                          // real part
        out[(size_t)B_SZ * N_SZ + idx] = x1i * q;    // imag part
    }
}

extern "C" void kernel_launch(void* const* d_in, const int* in_sizes, int n_in,
                              void* d_out, int out_size) {
    const float* Yr  = (const float*)d_in[0];
    const float* Yi  = (const float*)d_in[1];
    const float* xr  = (const float*)d_in[2];
    const float* xi  = (const float*)d_in[3];
    const float* xpr = (const float*)d_in[4];
    const float* xpi = (const float*)d_in[5];
    const float* d3w = (const float*)d_in[6];
    const float* d3b = (const float*)d_in[7];
    const float* w1  = (const float*)d_in[8];
    const float* b1  = (const float*)d_in[9];
    const float* w2  = (const float*)d_in[10];
    const float* b2  = (const float*)d_in[11];
    float* out = (float*)d_out;

    dim3 grid(N_SZ / WARPS_PER_BLOCK, B_SZ);
    fused_kernel<<<grid, THREADS>>>(Yr, Yi, xr, xi, xpr, xpi,
                                    d3w, d3b, w1, b1, w2, b2, out);
}